// round 1
// baseline (speedup 1.0000x reference)
#include <cuda_runtime.h>

#define NSPK 256
#define MU   64
#define DIM  1024
#define ROWS (NSPK * MU)

#define BM 128
#define BN 128
#define BK 16

// Scratch (device globals — no allocation allowed)
__device__ float g_S[NSPK * DIM];     // per-speaker sums  (256 x 1024)
__device__ float g_Sn2[NSPK];         // ||S_j||^2
__device__ float g_invS[NSPK];        // 1/||S_j|| (via the reference's exact l2norm form)
__device__ float g_rn[ROWS];          // ||emb_r||^2 per utterance row

// ---------------------------------------------------------------------------
// Kernel 1: per-speaker sums over M=64 utterances + ||S||^2
// grid = 256 (one block per speaker), block = 256 threads (4 columns each)
// ---------------------------------------------------------------------------
__global__ __launch_bounds__(256) void k_sums(const float* __restrict__ in) {
    int j = blockIdx.x;
    int t = threadIdx.x;
    const float* base = in + (size_t)j * MU * DIM;

    float s0 = 0.f, s1 = 0.f, s2 = 0.f, s3 = 0.f;
#pragma unroll 8
    for (int m = 0; m < MU; m++) {
        const float* r = base + m * DIM;
        s0 += r[t];
        s1 += r[t + 256];
        s2 += r[t + 512];
        s3 += r[t + 768];
    }
    g_S[j * DIM + t]       = s0;
    g_S[j * DIM + t + 256] = s1;
    g_S[j * DIM + t + 512] = s2;
    g_S[j * DIM + t + 768] = s3;

    float sq = s0 * s0 + s1 * s1 + s2 * s2 + s3 * s3;
#pragma unroll
    for (int o = 16; o > 0; o >>= 1)
        sq += __shfl_xor_sync(0xffffffffu, sq, o);

    __shared__ float red[8];
    if ((t & 31) == 0) red[t >> 5] = sq;
    __syncthreads();
    if (t == 0) {
        float tot = 0.f;
#pragma unroll
        for (int i = 0; i < 8; i++) tot += red[i];
        g_Sn2[j] = tot;
        // center = (S/64) * rsqrt(max(||S/64||^2, 1e-12))  ->  S * g_invS
        g_invS[j] = rsqrtf(fmaxf(tot * (1.0f / 4096.0f), 1e-12f)) * (1.0f / 64.0f);
    }
}

// ---------------------------------------------------------------------------
// Kernel 2: per-row squared norms. One warp per row, 8 rows per block.
// grid = 2048, block = 256
// ---------------------------------------------------------------------------
__global__ __launch_bounds__(256) void k_rownorm(const float* __restrict__ in) {
    int warp = threadIdx.x >> 5;
    int lane = threadIdx.x & 31;
    int r = blockIdx.x * 8 + warp;

    const float4* p = (const float4*)(in + (size_t)r * DIM);
    float s = 0.f;
#pragma unroll
    for (int i = 0; i < 8; i++) {
        float4 v = p[lane + i * 32];
        s += v.x * v.x + v.y * v.y + v.z * v.z + v.w * v.w;
    }
#pragma unroll
    for (int o = 16; o > 0; o >>= 1)
        s += __shfl_xor_sync(0xffffffffu, s, o);
    if (lane == 0) g_rn[r] = s;
}

// ---------------------------------------------------------------------------
// Kernel 3: GEMM  G = emb (16384x1024) . S^T (1024x256)  with fused epilogue.
// 128x128 tile, BK=16, 256 threads, 8x8 per thread.
// grid = (128, 2)
// ---------------------------------------------------------------------------
__global__ __launch_bounds__(256) void k_gemm(const float* __restrict__ A,
                                              float* __restrict__ out,
                                              const float* __restrict__ wp,
                                              const float* __restrict__ bp) {
    __shared__ float As[BK][BM + 4];
    __shared__ float Bs[BK][BN + 4];

    int tid = threadIdx.x;
    int bm0 = blockIdx.x * BM;
    int bn0 = blockIdx.y * BN;
    int tx = tid & 15;   // 0..15 -> output cols tx*8 .. tx*8+7
    int ty = tid >> 4;   // 0..15 -> output rows ty*8 .. ty*8+7

    int lr = tid >> 2;        // 0..63 : tile row for loading
    int lk = (tid & 3) * 4;   // 0,4,8,12 : k offset (float4)

    float acc[8][8] = {};

    const float* Abase = A   + (size_t)(bm0 + lr) * DIM + lk;
    const float* Bbase = g_S + (size_t)(bn0 + lr) * DIM + lk;

    for (int k0 = 0; k0 < DIM; k0 += BK) {
        // ---- load 128x16 tiles of A and B(=S), transposed into smem ----
#pragma unroll
        for (int p = 0; p < 2; p++) {
            float4 va = *(const float4*)(Abase + (size_t)p * 64 * DIM + k0);
            float4 vb = *(const float4*)(Bbase + (size_t)p * 64 * DIM + k0);
            int row = lr + p * 64;
            As[lk + 0][row] = va.x; As[lk + 1][row] = va.y;
            As[lk + 2][row] = va.z; As[lk + 3][row] = va.w;
            Bs[lk + 0][row] = vb.x; Bs[lk + 1][row] = vb.y;
            Bs[lk + 2][row] = vb.z; Bs[lk + 3][row] = vb.w;
        }
        __syncthreads();

        // ---- 8x8 outer-product accumulation over BK ----
#pragma unroll
        for (int k = 0; k < BK; k++) {
            float a[8], bb[8];
#pragma unroll
            for (int i = 0; i < 8; i++) a[i]  = As[k][ty * 8 + i];
#pragma unroll
            for (int j = 0; j < 8; j++) bb[j] = Bs[k][tx * 8 + j];
#pragma unroll
            for (int i = 0; i < 8; i++)
#pragma unroll
                for (int j = 0; j < 8; j++)
                    acc[i][j] = fmaf(a[i], bb[j], acc[i][j]);
        }
        __syncthreads();
    }

    // ---- fused epilogue ----
    float w = *wp;
    float bc = *bp;
    int r0 = bm0 + ty * 8;
    int c0 = bn0 + tx * 8;

#pragma unroll
    for (int i = 0; i < 8; i++) {
        int r = r0 + i;
        int jspk = r >> 6;           // speaker of this utterance row
        float rn = g_rn[r];
        float* orow = out + (size_t)r * NSPK + c0;
#pragma unroll
        for (int j = 0; j < 8; j++) {
            int c = c0 + j;
            float G = acc[i][j];
            float val;
            if (c == jspk) {
                // dot(e, l2norm(S_j - e)) = (G - ||e||^2)/sqrt(max(||S||^2 - 2G + ||e||^2, eps))
                float den2 = fmaxf(g_Sn2[c] - 2.0f * G + rn, 1e-12f);
                val = (G - rn) * rsqrtf(den2);
            } else {
                val = G * g_invS[c];
            }
            orow[j] = fmaf(w, val, bc);
        }
    }
}

// ---------------------------------------------------------------------------
extern "C" void kernel_launch(void* const* d_in, const int* in_sizes, int n_in,
                              void* d_out, int out_size) {
    const float* in = (const float*)d_in[0];
    const float* w  = (const float*)d_in[1];
    const float* b  = (const float*)d_in[2];
    float* out = (float*)d_out;

    (void)in_sizes; (void)n_in; (void)out_size;

    k_sums<<<NSPK, 256>>>(in);
    k_rownorm<<<ROWS / 8, 256>>>(in);
    k_gemm<<<dim3(ROWS / BM, NSPK / BN), 256>>>(in, out, w, b);
}

// round 5
// speedup vs baseline: 2.5661x; 2.5661x over previous
#include <cuda_runtime.h>
#include <cuda_bf16.h>
#include <cstdint>

#define NSPK 256
#define MU   64
#define DIM  1024
#define ROWS (NSPK * MU)

#define BM 128
#define BN 256
#define KC 32
#define NCHUNK (DIM / KC)     // 32

// smem tile layout (per buffer), row stride 80B (64B data + 16B pad, 16B aligned)
#define ASTRIDE 80
#define AHI_OFF 0
#define ALO_OFF (128 * ASTRIDE)          // 10240
#define BHI_OFF (2 * 128 * ASTRIDE)      // 20480
#define BLO_OFF (BHI_OFF + 256 * ASTRIDE)// 40960
#define BUFSZ   (BLO_OFF + 256 * ASTRIDE)// 61440
#define SMEM_TOTAL (2 * BUFSZ)           // 122880

// ---- device scratch (no allocation allowed) ----
__device__ float         g_Spart[4 * NSPK * DIM];
__device__ __nv_bfloat16 g_Shi[NSPK * DIM];
__device__ __nv_bfloat16 g_Slo[NSPK * DIM];
__device__ float         g_Sn2[NSPK];
__device__ float         g_invS[NSPK];

// ============================ PTX helpers (sm_80-era, no "a" features) ======
__device__ __forceinline__ uint32_t smem_u32(const void* p) {
    uint32_t a;
    asm("{ .reg .u64 t; cvta.to.shared.u64 t, %1; cvt.u32.u64 %0, t; }" : "=r"(a) : "l"(p));
    return a;
}

__device__ __forceinline__ void ldsm_x4(uint32_t* r, uint32_t addr) {
    asm volatile("ldmatrix.sync.aligned.m8n8.x4.shared.b16 {%0,%1,%2,%3}, [%4];"
                 : "=r"(r[0]), "=r"(r[1]), "=r"(r[2]), "=r"(r[3]) : "r"(addr));
}

__device__ __forceinline__ void mma16816(float* d, const uint32_t* a, const uint32_t* b) {
    asm volatile(
        "mma.sync.aligned.m16n8k16.row.col.f32.bf16.bf16.f32 "
        "{%0,%1,%2,%3}, {%4,%5,%6,%7}, {%8,%9}, {%0,%1,%2,%3};"
        : "+f"(d[0]), "+f"(d[1]), "+f"(d[2]), "+f"(d[3])
        : "r"(a[0]), "r"(a[1]), "r"(a[2]), "r"(a[3]), "r"(b[0]), "r"(b[1]));
}

__device__ __forceinline__ void cp_async16(uint32_t dst, const void* src) {
    asm volatile("cp.async.cg.shared.global [%0], [%1], 16;"
                 :: "r"(dst), "l"(src) : "memory");
}
#define CP_COMMIT() asm volatile("cp.async.commit_group;" ::: "memory")
#define CP_WAIT0()  asm volatile("cp.async.wait_group 0;" ::: "memory")

// pack two floats -> bf16x2 (x low, y high)
__device__ __forceinline__ uint32_t pack_bf16x2(float x, float y) {
    uint32_t r;
    asm("cvt.rn.bf16x2.f32 %0, %1, %2;" : "=r"(r) : "f"(y), "f"(x));
    return r;
}
__device__ __forceinline__ float bf_lo(uint32_t p) { return __uint_as_float(p << 16); }
__device__ __forceinline__ float bf_hi(uint32_t p) { return __uint_as_float(p & 0xffff0000u); }

// ============================ Kernel 1: partial speaker sums ================
__global__ __launch_bounds__(256) void k_sums(const float* __restrict__ in) {
    int b = blockIdx.x;                 // spk = b>>2, quarter = b&3
    int t = threadIdx.x;
    const float* base = in + ((size_t)(b >> 2) * MU + (size_t)(b & 3) * 16) * DIM;

    float s0 = 0.f, s1 = 0.f, s2 = 0.f, s3 = 0.f;
#pragma unroll
    for (int m = 0; m < 16; m++) {
        const float* r = base + m * DIM;
        s0 += r[t]; s1 += r[t + 256]; s2 += r[t + 512]; s3 += r[t + 768];
    }
    float* o = g_Spart + (size_t)b * DIM;
    o[t] = s0; o[t + 256] = s1; o[t + 512] = s2; o[t + 768] = s3;
}

// ============================ Kernel 2: finalize S -> bf16 hi/lo + norms ====
__global__ __launch_bounds__(256) void k_finish() {
    int j = blockIdx.x;
    int t = threadIdx.x;
    float sq = 0.f;

#pragma unroll
    for (int q = 0; q < 4; q++) {
        int c = t + q * 256;
        float s = 0.f;
#pragma unroll
        for (int p = 0; p < 4; p++)
            s += g_Spart[((size_t)j * 4 + p) * DIM + c];
        __nv_bfloat16 h = __float2bfloat16(s);
        g_Shi[(size_t)j * DIM + c] = h;
        g_Slo[(size_t)j * DIM + c] = __float2bfloat16(s - __bfloat162float(h));
        sq = fmaf(s, s, sq);
    }
#pragma unroll
    for (int o = 16; o > 0; o >>= 1)
        sq += __shfl_xor_sync(0xffffffffu, sq, o);

    __shared__ float red[8];
    if ((t & 31) == 0) red[t >> 5] = sq;
    __syncthreads();
    if (t == 0) {
        float tot = 0.f;
#pragma unroll
        for (int i = 0; i < 8; i++) tot += red[i];
        g_Sn2[j] = tot;
        g_invS[j] = rsqrtf(fmaxf(tot * (1.0f / 4096.0f), 1e-12f)) * (1.0f / 64.0f);
    }
}

// ============================ Kernel 3: HMMA GEMM + fused epilogue ==========
// grid = 128, block = 512 (16 warps, 4x4 warp grid, warp tile 32x64)
__global__ __launch_bounds__(512, 1)
void k_gemm(const float* __restrict__ A, float* __restrict__ out,
            const float* __restrict__ wp, const float* __restrict__ bp) {
    extern __shared__ char smem[];
    __shared__ float rn4[128][4];

    uint32_t sb = smem_u32(smem);
    int t = threadIdx.x;
    int wid = t >> 5;
    int L = t & 31;
    int warp_m = wid & 3;         // 0..3 -> M offset *32
    int warp_n = wid >> 2;        // 0..3 -> N offset *64
    int bm0 = blockIdx.x * BM;

    // ---- per-thread staging mapping ----
    int row_a = t >> 2;           // 0..127
    int seg   = t & 3;            // 0..3, cols seg*8..seg*8+7
    const float* ap = A + ((size_t)(bm0 + row_a)) * DIM + seg * 8;
    uint32_t a_sts = sb + AHI_OFF + row_a * ASTRIDE + seg * 16;   // +ALO delta for lo

    // ---- per-thread ldmatrix lane addresses (byte offsets within tile) ----
    int li = L >> 3;              // matrix index 0..3
    int lr = L & 7;               // row within 8x8
    // A: matrices {0:(m+0,k+0),1:(m+8,k+0),2:(m+0,k+8),3:(m+8,k+8)}
    uint32_t a_off = (uint32_t)((warp_m * 32 + (li & 1) * 8 + lr) * ASTRIDE + (li >> 1) * 16);
    // B: matrices {0:(n+0,k+0),1:(n+0,k+8),2:(n+8,k+0),3:(n+8,k+8)}
    uint32_t b_off = (uint32_t)((warp_n * 64 + (li >> 1) * 8 + lr) * ASTRIDE + (li & 1) * 16);

    float acc[2][8][4];
#pragma unroll
    for (int i = 0; i < 2; i++)
#pragma unroll
        for (int j = 0; j < 8; j++)
#pragma unroll
            for (int k = 0; k < 4; k++) acc[i][j][k] = 0.f;

    float sq = 0.f;

    // ---------------- staging helpers (inlined manually) ----------------
    // B cp.async: 4 granules per thread
    auto issue_B = [&](int k0, int buf) {
#pragma unroll
        for (int i = 0; i < 4; i++) {
            int g = t + 512 * i;             // 0..2047
            int tile = g >> 10;              // 0: hi, 1: lo
            int rb = (g >> 2) & 255;         // speaker row
            int sg = g & 3;
            const __nv_bfloat16* src =
                (tile ? g_Slo : g_Shi) + (size_t)rb * DIM + k0 + sg * 8;
            uint32_t dst = sb + buf * BUFSZ + (tile ? BLO_OFF : BHI_OFF)
                         + rb * ASTRIDE + sg * 16;
            cp_async16(dst, src);
        }
        CP_COMMIT();
    };

    // ---------------- prologue: stage chunk 0 ----------------
    {
        issue_B(0, 0);
        float4 v0 = *(const float4*)(ap);
        float4 v1 = *(const float4*)(ap + 4);
        sq += v0.x*v0.x + v0.y*v0.y + v0.z*v0.z + v0.w*v0.w
            + v1.x*v1.x + v1.y*v1.y + v1.z*v1.z + v1.w*v1.w;
        uint32_t h01 = pack_bf16x2(v0.x, v0.y), h23 = pack_bf16x2(v0.z, v0.w);
        uint32_t h45 = pack_bf16x2(v1.x, v1.y), h67 = pack_bf16x2(v1.z, v1.w);
        uint32_t l01 = pack_bf16x2(v0.x - bf_lo(h01), v0.y - bf_hi(h01));
        uint32_t l23 = pack_bf16x2(v0.z - bf_lo(h23), v0.w - bf_hi(h23));
        uint32_t l45 = pack_bf16x2(v1.x - bf_lo(h45), v1.y - bf_hi(h45));
        uint32_t l67 = pack_bf16x2(v1.z - bf_lo(h67), v1.w - bf_hi(h67));
        *(uint4*)(smem + AHI_OFF + row_a * ASTRIDE + seg * 16) = make_uint4(h01, h23, h45, h67);
        *(uint4*)(smem + ALO_OFF + row_a * ASTRIDE + seg * 16) = make_uint4(l01, l23, l45, l67);
        CP_WAIT0();
        __syncthreads();
    }

    // ---------------- main loop ----------------
    for (int c = 0; c < NCHUNK; c++) {
        int cur = c & 1;
        int nxt = cur ^ 1;
        float4 v0, v1;
        bool more = (c + 1 < NCHUNK);

        if (more) {
            issue_B((c + 1) * KC, nxt);
            const float* app = ap + (c + 1) * KC;
            v0 = *(const float4*)(app);
            v1 = *(const float4*)(app + 4);
        }

        // ---- compute 3 phases on cur ----
        uint32_t tbase = sb + cur * BUFSZ;
#pragma unroll
        for (int ph = 0; ph < 3; ph++) {
            uint32_t abase = tbase + (ph == 1 ? ALO_OFF : AHI_OFF) + a_off;
            uint32_t bbase = tbase + (ph == 2 ? BLO_OFF : BHI_OFF) + b_off;
#pragma unroll
            for (int ks = 0; ks < 2; ks++) {
                uint32_t af0[4], af1[4];
                ldsm_x4(af0, abase + ks * 32);
                ldsm_x4(af1, abase + ks * 32 + 16 * ASTRIDE);
#pragma unroll
                for (int ntp = 0; ntp < 4; ntp++) {
                    uint32_t bf[4];
                    ldsm_x4(bf, bbase + ks * 32 + ntp * 16 * ASTRIDE);
                    mma16816(acc[0][ntp * 2 + 0], af0, bf + 0);
                    mma16816(acc[0][ntp * 2 + 1], af0, bf + 2);
                    mma16816(acc[1][ntp * 2 + 0], af1, bf + 0);
                    mma16816(acc[1][ntp * 2 + 1], af1, bf + 2);
                }
            }
        }

        if (more) {
            sq += v0.x*v0.x + v0.y*v0.y + v0.z*v0.z + v0.w*v0.w
                + v1.x*v1.x + v1.y*v1.y + v1.z*v1.z + v1.w*v1.w;
            uint32_t h01 = pack_bf16x2(v0.x, v0.y), h23 = pack_bf16x2(v0.z, v0.w);
            uint32_t h45 = pack_bf16x2(v1.x, v1.y), h67 = pack_bf16x2(v1.z, v1.w);
            uint32_t l01 = pack_bf16x2(v0.x - bf_lo(h01), v0.y - bf_hi(h01));
            uint32_t l23 = pack_bf16x2(v0.z - bf_lo(h23), v0.w - bf_hi(h23));
            uint32_t l45 = pack_bf16x2(v1.x - bf_lo(h45), v1.y - bf_hi(h45));
            uint32_t l67 = pack_bf16x2(v1.z - bf_lo(h67), v1.w - bf_hi(h67));
            char* nb = smem + nxt * BUFSZ;
            *(uint4*)(nb + AHI_OFF + row_a * ASTRIDE + seg * 16) = make_uint4(h01, h23, h45, h67);
            *(uint4*)(nb + ALO_OFF + row_a * ASTRIDE + seg * 16) = make_uint4(l01, l23, l45, l67);
            CP_WAIT0();
        }
        __syncthreads();
    }

    // ---------------- row sqnorm reduction ----------------
    rn4[row_a][seg] = sq;
    __syncthreads();

    // ---------------- epilogue ----------------
    float w  = __ldg(wp);
    float bc = __ldg(bp);

#pragma unroll
    for (int mt = 0; mt < 2; mt++) {
#pragma unroll
        for (int h = 0; h < 2; h++) {
            int row_t = warp_m * 32 + mt * 16 + (L >> 2) + h * 8;
            int r = bm0 + row_t;
            int spk = r >> 6;
            float rn = rn4[row_t][0] + rn4[row_t][1] + rn4[row_t][2] + rn4[row_t][3];
            float sn2_spk = __ldg(&g_Sn2[spk]);
            float* orow = out + (size_t)r * NSPK;
#pragma unroll
            for (int nt = 0; nt < 8; nt++) {
                int c0 = warp_n * 64 + nt * 8 + (L & 3) * 2;
                float G0 = acc[mt][nt][h * 2 + 0];
                float G1 = acc[mt][nt][h * 2 + 1];
                float v0, v1;
                if (c0 == spk) {
                    float den = fmaxf(sn2_spk - 2.0f * G0 + rn, 1e-12f);
                    v0 = (G0 - rn) * rsqrtf(den);
                } else {
                    v0 = G0 * __ldg(&g_invS[c0]);
                }
                if (c0 + 1 == spk) {
                    float den = fmaxf(sn2_spk - 2.0f * G1 + rn, 1e-12f);
                    v1 = (G1 - rn) * rsqrtf(den);
                } else {
                    v1 = G1 * __ldg(&g_invS[c0 + 1]);
                }
                *(float2*)(orow + c0) = make_float2(fmaf(w, v0, bc), fmaf(w, v1, bc));
            }
        }
    }
}

// ============================================================================
extern "C" void kernel_launch(void* const* d_in, const int* in_sizes, int n_in,
                              void* d_out, int out_size) {
    const float* in = (const float*)d_in[0];
    const float* w  = (const float*)d_in[1];
    const float* b  = (const float*)d_in[2];
    float* out = (float*)d_out;
    (void)in_sizes; (void)n_in; (void)out_size;

    cudaFuncSetAttribute(k_gemm, cudaFuncAttributeMaxDynamicSharedMemorySize, SMEM_TOTAL);

    k_sums<<<1024, 256>>>(in);
    k_finish<<<256, 256>>>();
    k_gemm<<<ROWS / BM, 512, SMEM_TOTAL>>>(in, out, w, b);
}